// round 13
// baseline (speedup 1.0000x reference)
#include <cuda_runtime.h>
#include <cuda_bf16.h>
#include <math.h>

// Problem constants
#define NQ   10
#define DIM  1024        // 2^NQ
#define NT   32
#define DM   512
#define NB   128         // batch
#define NPQC 40
#define NSIM (NB * NT)   // 4096 statevector sims per pass

typedef unsigned long long ull;

// ---------------- device scratch (static globals, no allocation) -------------
__device__ float2 d_part1[(size_t)NB * 4 * DIM]; // pass-1 per-CTA LCU partials (4 MB)
__device__ float2 d_part2[(size_t)NB * 4 * DIM]; // pass-2 per-CTA LCU partials (4 MB)
__device__ float2 d_gt[(size_t)NSIM * NPQC];     // per-(b,l) gate (cos,sin) tables
__device__ float2 d_lcuW[NT];                    // normalized LCU weights

// Gate encoding: bit0 = type (0=RY, 1=CRX); bits[1..4] = RY bit position or
// CRX control position; bits[5..8] = CRX target position.
// Bit position p of qubit wire w is p = 9 - w (reference is big-endian).
#define RYG(p)      ((unsigned)((p) << 1))
#define CXG(cp, tp) ((unsigned)(1u | ((cp) << 1) | ((tp) << 5)))

#define GATE_LIST                                                              \
        RYG(9), RYG(8), RYG(7), RYG(6), RYG(5), RYG(4), RYG(3), RYG(2),        \
        RYG(1), RYG(0),                                                        \
        CXG(0, 9), CXG(1, 0), CXG(2, 1), CXG(3, 2), CXG(4, 3),                 \
        CXG(5, 4), CXG(6, 5), CXG(7, 6), CXG(8, 7), CXG(9, 8),                 \
        RYG(9), RYG(8), RYG(7), RYG(6), RYG(5), RYG(4), RYG(3), RYG(2),        \
        RYG(1), RYG(0),                                                        \
        CXG(0, 1), CXG(9, 0), CXG(8, 9), CXG(7, 8), CXG(6, 7),                 \
        CXG(5, 6), CXG(4, 5), CXG(3, 4), CXG(2, 3), CXG(1, 2)

// ---------------- packed f32x2 helpers (sm_103a; PTX-only FFMA2) -------------
__device__ __forceinline__ ull pk2(float lo, float hi) {
    ull v;
    asm("mov.b64 %0, {%1,%2};" : "=l"(v) : "f"(lo), "f"(hi));
    return v;
}

// RY butterfly (componentwise): a0' = c*a0 - s*a1 ; a1' = s*a0 + c*a1
// C2=(c,c) S2=(s,s) N2=(-s,-s)
__device__ __forceinline__ void bfly_ry2(float2& a0, float2& a1,
                                         ull C2, ull S2, ull N2)
{
    asm("{\n\t"
        ".reg .b64 A,B,T,U;\n\t"
        "mov.b64 A, {%0,%1};\n\t"
        "mov.b64 B, {%2,%3};\n\t"
        "mul.rn.f32x2 T, %4, A;\n\t"
        "fma.rn.f32x2 T, %6, B, T;\n\t"
        "mul.rn.f32x2 U, %5, A;\n\t"
        "fma.rn.f32x2 U, %4, B, U;\n\t"
        "mov.b64 {%0,%1}, T;\n\t"
        "mov.b64 {%2,%3}, U;\n\t"
        "}"
        : "+f"(a0.x), "+f"(a0.y), "+f"(a1.x), "+f"(a1.y)
        : "l"(C2), "l"(S2), "l"(N2));
}

// RY lane update: a' = c*a + se*p   (p = shfl partner, se carries the sign)
__device__ __forceinline__ void ry_lane2(float2& a, ull C2, ull SE2,
                                         float px, float py)
{
    asm("{\n\t"
        ".reg .b64 A,P,T;\n\t"
        "mov.b64 A, {%0,%1};\n\t"
        "mov.b64 P, {%2,%3};\n\t"
        "mul.rn.f32x2 T, %4, A;\n\t"
        "fma.rn.f32x2 T, %5, P, T;\n\t"
        "mov.b64 {%0,%1}, T;\n\t"
        "}"
        : "+f"(a.x), "+f"(a.y)
        : "f"(px), "f"(py), "l"(C2), "l"(SE2));
}

// RX butterfly: a0' = c*a0 + s*(a1.y,-a1.x) ; a1' = c*a1 + s*(a0.y,-a0.x)
__device__ __forceinline__ void bfly_rx2(float2& a0, float2& a1,
                                         ull C2, ull S2)
{
    asm("{\n\t"
        ".reg .b64 A,B,V,U,T,W;\n\t"
        ".reg .f32 nx,ny;\n\t"
        "neg.f32 nx, %2;\n\t"
        "neg.f32 ny, %0;\n\t"
        "mov.b64 A, {%0,%1};\n\t"
        "mov.b64 B, {%2,%3};\n\t"
        "mov.b64 V, {%3, nx};\n\t"
        "mov.b64 U, {%1, ny};\n\t"
        "mul.rn.f32x2 T, %4, A;\n\t"
        "fma.rn.f32x2 T, %5, V, T;\n\t"
        "mul.rn.f32x2 W, %4, B;\n\t"
        "fma.rn.f32x2 W, %5, U, W;\n\t"
        "mov.b64 {%0,%1}, T;\n\t"
        "mov.b64 {%2,%3}, W;\n\t"
        "}"
        : "+f"(a0.x), "+f"(a0.y), "+f"(a1.x), "+f"(a1.y)
        : "l"(C2), "l"(S2));
}

// RX lane update: a' = c*a + s*(py,-px)
__device__ __forceinline__ void rx_lane2(float2& a, ull C2, ull S2,
                                         float px, float py)
{
    asm("{\n\t"
        ".reg .b64 A,V,T;\n\t"
        ".reg .f32 nx;\n\t"
        "neg.f32 nx, %2;\n\t"
        "mov.b64 A, {%0,%1};\n\t"
        "mov.b64 V, {%3, nx};\n\t"
        "mul.rn.f32x2 T, %4, A;\n\t"
        "fma.rn.f32x2 T, %5, V, T;\n\t"
        "mov.b64 {%0,%1}, T;\n\t"
        "}"
        : "+f"(a.x), "+f"(a.y)
        : "f"(px), "f"(py), "l"(C2), "l"(S2));
}

// ---- register-resident circuit: lane L slot r holds amplitude g = r*32+L ----
//   g bits 5..9 -> register bits (packed-f32x2 FFMA butterflies)
//   g bits 0..4 -> lane bits (partner via shfl.xor; controls fold into coeffs)
__device__ __forceinline__ void apply_circuit_reg(float2 a[32],
                                                  const float2* __restrict__ g,
                                                  int L)
{
    constexpr unsigned G[NPQC] = { GATE_LIST };
#pragma unroll
    for (int k = 0; k < NPQC; ++k) {
        const unsigned e = G[k];
        const float cth = g[k].x;
        const float sth = g[k].y;
        if (!(e & 1u)) {
            const int p = (int)((e >> 1) & 15u);
            if (p >= 5) {
                // RY on register bit
                const int rb = 1 << (p - 5);
                const ull C2 = pk2(cth, cth);
                const ull S2 = pk2(sth, sth);
                const ull N2 = pk2(-sth, -sth);
#pragma unroll
                for (int r0 = 0; r0 < 32; ++r0)
                    if (!(r0 & rb))
                        bfly_ry2(a[r0], a[r0 | rb], C2, S2, N2);
            } else {
                // RY on lane bit: a' = c*a + se*partner, se = bit? +s : -s
                const int lb = 1 << p;
                const float se = (L & lb) ? sth : -sth;
                const ull C2  = pk2(cth, cth);
                const ull SE2 = pk2(se, se);
#pragma unroll
                for (int r = 0; r < 32; ++r) {
                    const float px = __shfl_xor_sync(0xffffffffu, a[r].x, lb);
                    const float py = __shfl_xor_sync(0xffffffffu, a[r].y, lb);
                    ry_lane2(a[r], C2, SE2, px, py);
                }
            }
        } else {
            const int cp = (int)((e >> 1) & 15u);
            const int tp = (int)((e >> 5) & 15u);
            if (tp >= 5) {
                const int rb = 1 << (tp - 5);
                if (cp >= 5) {
                    // control is a register bit: folds at compile time
                    const int cb = 1 << (cp - 5);
                    const ull C2 = pk2(cth, cth);
                    const ull S2 = pk2(sth, sth);
#pragma unroll
                    for (int r0 = 0; r0 < 32; ++r0)
                        if (!(r0 & rb) && (r0 & cb))
                            bfly_rx2(a[r0], a[r0 | rb], C2, S2);
                } else {
                    // lane-bit control folded into coefficients
                    const bool act = (L >> cp) & 1;
                    const float ce = act ? cth : 1.f;
                    const float se = act ? sth : 0.f;
                    const ull C2 = pk2(ce, ce);
                    const ull S2 = pk2(se, se);
#pragma unroll
                    for (int r0 = 0; r0 < 32; ++r0)
                        if (!(r0 & rb))
                            bfly_rx2(a[r0], a[r0 | rb], C2, S2);
                }
            } else {
                // RX on lane bit
                const int lb = 1 << tp;
                if (cp >= 5) {
                    const int cb = 1 << (cp - 5);
                    const ull C2 = pk2(cth, cth);
                    const ull S2 = pk2(sth, sth);
#pragma unroll
                    for (int r = 0; r < 32; ++r) {
                        if (r & cb) {
                            const float px = __shfl_xor_sync(0xffffffffu, a[r].x, lb);
                            const float py = __shfl_xor_sync(0xffffffffu, a[r].y, lb);
                            rx_lane2(a[r], C2, S2, px, py);
                        }
                    }
                } else {
                    const bool act = (L >> cp) & 1;
                    const float ce = act ? cth : 1.f;
                    const float se = act ? sth : 0.f;
                    const ull C2 = pk2(ce, ce);
                    const ull S2 = pk2(se, se);
#pragma unroll
                    for (int r = 0; r < 32; ++r) {
                        const float px = __shfl_xor_sync(0xffffffffu, a[r].x, lb);
                        const float py = __shfl_xor_sync(0xffffffffu, a[r].y, lb);
                        rx_lane2(a[r], C2, S2, px, py);
                    }
                }
            }
        }
    }
}

// ----------------------------- kernels --------------------------------------

// pqc_params = tokens @ W.T + b -> (cos, sin) of theta/2 per gate.
// One block per (b,l) row; 256 threads; float4-vectorized dots. (R7-verified.)
// Block 0 additionally computes the normalized LCU weights (warp 0).
__global__ void params_kernel(const float* __restrict__ tokens,
                              const float* __restrict__ W,
                              const float* __restrict__ bias,
                              const float* __restrict__ lre,
                              const float* __restrict__ lim)
{
    const int blk = blockIdx.x;                 // b*32 + l
    const int tid = threadIdx.x;

    if (blk == 0 && tid < 32) {
        const float r = lre[tid], i = lim[tid];
        const float a = sqrtf(r * r + i * i);
        float ssum = a;
#pragma unroll
        for (int o = 16; o; o >>= 1) ssum += __shfl_xor_sync(0xffffffffu, ssum, o);
        d_lcuW[tid] = make_float2(r / ssum, i / ssum);
    }

    __shared__ float4 sh4[DM / 4];              // 128 float4 = 512 floats
    const float4* row4 = (const float4*)(tokens + (size_t)blk * DM);
    if (tid < DM / 4) sh4[tid] = row4[tid];
    __syncthreads();

    const int warp = tid >> 5;
    const int lane = tid & 31;
    for (int k = warp; k < NPQC; k += 8) {
        const float4* w4 = (const float4*)(W + (size_t)k * DM);
        float acc = 0.f;
#pragma unroll
        for (int j = 0; j < 4; ++j) {
            const int idx = lane + j * 32;
            const float4 t = sh4[idx];
            const float4 ww = __ldg(w4 + idx);
            acc += t.x * ww.x + t.y * ww.y + t.z * ww.z + t.w * ww.w;
        }
#pragma unroll
        for (int o = 16; o; o >>= 1) acc += __shfl_xor_sync(0xffffffffu, acc, o);
        if (lane == 0) {
            const float h = 0.5f * (acc + __ldg(bias + k));
            d_gt[(size_t)blk * NPQC + k] = make_float2(cosf(h), sinf(h));
        }
    }
}

// Warp-per-statevector simulator. One CTA = 8 warps = 8 consecutive l-values
// of one batch. Pass 2 rebuilds the monomial state from the 4 pass-1 partials
// (smem-staged, summed once per CTA). The LCU-weighted sum over the CTA's 8
// l's is reduced in smem and written to the pass's partial buffer.
template <bool FIRST>
__global__ void __launch_bounds__(256, 2) wsim_kernel()
{
    const int blk = blockIdx.x;          // b*4 + c
    const int b   = blk >> 2;
    const int c   = blk & 3;
    const int tid = threadIdx.x;         // 256
    const int w   = tid >> 5;            // warp 0..7
    const int L   = tid & 31;
    const int l   = c * 8 + w;

    __shared__ float2 sg[8][NPQC];       // gate tables (2.5 KB)
    __shared__ float2 sbuf[4][DIM];      // staging / reduction slots (32 KB)

    // Load 8 gate tables (contiguous in d_gt) cooperatively.
    {
        const float2* gbase = d_gt + ((size_t)(b * NT + c * 8)) * NPQC;
        for (int i = tid; i < 8 * NPQC; i += 256)
            (&sg[0][0])[i] = gbase[i];
    }

    if (!FIRST) {
        // mono = sum of the batch's 4 pass-1 partials; stage in sbuf[0].
        for (int g = tid; g < DIM; g += 256) {
            float2 m = d_part1[(size_t)(b * 4 + 0) * DIM + g];
#pragma unroll
            for (int cc = 1; cc < 4; ++cc) {
                const float2 v = d_part1[(size_t)(b * 4 + cc) * DIM + g];
                m.x += v.x; m.y += v.y;
            }
            sbuf[0][g] = m;
        }
    }
    __syncthreads();

    float2 a[32];
    if (FIRST) {
#pragma unroll
        for (int r = 0; r < 32; ++r) a[r] = make_float2(0.f, 0.f);
        a[0].x = (L == 0) ? 1.f : 0.f;
    } else {
#pragma unroll
        for (int r = 0; r < 32; ++r) a[r] = sbuf[0][r * 32 + L];
    }
    __syncthreads();   // sbuf[0] reads complete before epilogue reuses sbuf

    apply_circuit_reg(a, sg[w], L);

    // ---- LCU weight + in-CTA reduction over the 8 warps --------------------
    const float2 wl = d_lcuW[l];
#pragma unroll
    for (int r = 0; r < 32; ++r) {
        const float2 v = a[r];
        a[r] = make_float2(wl.x * v.x - wl.y * v.y,
                           wl.x * v.y + wl.y * v.x);
    }
    // stage 1: warps 0-3 write their weighted state to slot w
    if (w < 4) {
#pragma unroll
        for (int r = 0; r < 32; ++r) sbuf[w][r * 32 + L] = a[r];
    }
    __syncthreads();
    // stage 2: warps 4-7 add into slot w-4
    if (w >= 4) {
        const int slot = w - 4;
#pragma unroll
        for (int r = 0; r < 32; ++r) {
            float2 v = sbuf[slot][r * 32 + L];
            v.x += a[r].x; v.y += a[r].y;
            sbuf[slot][r * 32 + L] = v;
        }
    }
    __syncthreads();
    // stage 3: 256 threads reduce the 4 slots, write the CTA partial
    float2* outp = (FIRST ? d_part1 : d_part2) + (size_t)blk * DIM;
#pragma unroll
    for (int j = 0; j < 4; ++j) {
        const int g = tid + j * 256;
        float2 m = sbuf[0][g];
#pragma unroll
        for (int wi = 1; wi < 4; ++wi) {
            m.x += sbuf[wi][g].x;
            m.y += sbuf[wi][g].y;
        }
        outp[g] = m;
    }
}

// -------- shared-memory circuit (used only by final_kernel, 128 CTAs) -------
__device__ __forceinline__ void apply_circuit_smem(float2* s, const float2* g, int tid)
{
    const unsigned G[NPQC] = { GATE_LIST };
#pragma unroll
    for (int k = 0; k < NPQC; ++k) {
        const unsigned e = G[k];
        const float c  = g[k].x;
        const float sn = g[k].y;
        if (!(e & 1u)) {
            const int p   = (int)((e >> 1) & 15u);
            const int bit = 1 << p;
            const int low = tid & (bit - 1);
            const int i0  = ((tid >> p) << (p + 1)) | low;
            const int i1  = i0 | bit;
            const float2 a0 = s[i0];
            const float2 a1 = s[i1];
            s[i0] = make_float2(c * a0.x - sn * a1.x, c * a0.y - sn * a1.y);
            s[i1] = make_float2(sn * a0.x + c * a1.x, sn * a0.y + c * a1.y);
        } else if (tid < 256) {
            const int cp = (int)((e >> 1) & 15u);
            const int tp = (int)((e >> 5) & 15u);
            const int pl = (cp < tp) ? cp : tp;
            const int ph = cp ^ tp ^ pl;
            const int bl = 1 << pl;
            const int bh = 1 << ph;
            const int low1 = tid & (bl - 1);
            const int t1   = ((tid >> pl) << (pl + 1)) | low1;
            const int low2 = t1 & (bh - 1);
            const int idx  = ((t1 >> ph) << (ph + 1)) | low2;
            const int i0   = idx | (1 << cp);
            const int i1   = i0 | (1 << tp);
            const float2 a0 = s[i0];
            const float2 a1 = s[i1];
            s[i0] = make_float2(c * a0.x + sn * a1.y, c * a0.y - sn * a1.x);
            s[i1] = make_float2(sn * a0.y + c * a1.x, c * a1.y - sn * a0.x);
        }
        __syncthreads();
    }
}

// Build QSVT accumulator from the 8 partials, normalize, apply feed-forward
// ansatz, measure X/Y/Z on all 10 wires. (R7-verified smem version.)
__global__ void __launch_bounds__(512) final_kernel(const float* __restrict__ qsvt,
                                                    const float* __restrict__ ffp,
                                                    float* __restrict__ out)
{
    const int b   = blockIdx.x;
    const int tid = threadIdx.x;         // 512

    __shared__ float2 s[DIM];
    __shared__ float2 g[NPQC];
    __shared__ float redx[16], redy[16], redz[16];

    const float c0 = qsvt[0], c1 = qsvt[1], c2 = qsvt[2];

    float2 a0, a1;
    {
        float2 m1a = make_float2(0.f, 0.f), m2a = make_float2(0.f, 0.f);
        float2 m1b = make_float2(0.f, 0.f), m2b = make_float2(0.f, 0.f);
#pragma unroll
        for (int c = 0; c < 4; ++c) {
            const size_t base = (size_t)(b * 4 + c) * DIM;
            float2 v;
            v = d_part1[base + tid];       m1a.x += v.x; m1a.y += v.y;
            v = d_part2[base + tid];       m2a.x += v.x; m2a.y += v.y;
            v = d_part1[base + tid + 512]; m1b.x += v.x; m1b.y += v.y;
            v = d_part2[base + tid + 512]; m2b.x += v.x; m2b.y += v.y;
        }
        a0 = make_float2(c1 * m1a.x + c2 * m2a.x + (tid == 0 ? c0 : 0.f),
                         c1 * m1a.y + c2 * m2a.y);
        a1 = make_float2(c1 * m1b.x + c2 * m2b.x,
                         c1 * m1b.y + c2 * m2b.y);
    }

    if (tid < NPQC) {
        const float h = 0.5f * ffp[tid];
        g[tid] = make_float2(cosf(h), sinf(h));
    }

    // L2 norm (constant QSVT scale cancels in normalization)
    float nn = a0.x * a0.x + a0.y * a0.y + a1.x * a1.x + a1.y * a1.y;
#pragma unroll
    for (int o = 16; o; o >>= 1) nn += __shfl_xor_sync(0xffffffffu, nn, o);
    if ((tid & 31) == 0) redx[tid >> 5] = nn;
    __syncthreads();
    if (tid < 32) {
        float v = (tid < 16) ? redx[tid] : 0.f;
#pragma unroll
        for (int o = 8; o; o >>= 1) v += __shfl_xor_sync(0xffffffffu, v, o);
        if (tid == 0) redx[0] = rsqrtf(v);
    }
    __syncthreads();
    const float sc = redx[0];
    s[tid]       = make_float2(a0.x * sc, a0.y * sc);
    s[tid + 512] = make_float2(a1.x * sc, a1.y * sc);
    __syncthreads();

    apply_circuit_smem(s, g, tid);

    // measurement: per wire w, pairs split on bit p = 9-w
#pragma unroll
    for (int w = 0; w < NQ; ++w) {
        const int p   = 9 - w;
        const int bit = 1 << p;
        const int low = tid & (bit - 1);
        const int i0  = ((tid >> p) << (p + 1)) | low;
        const int i1  = i0 | bit;
        const float2 v0 = s[i0];
        const float2 v1 = s[i1];
        float xr = v0.x * v1.x + v0.y * v1.y;             // Re(conj(a0)*a1)
        float yi = v0.x * v1.y - v0.y * v1.x;             // Im(conj(a0)*a1)
        float zz = v0.x * v0.x + v0.y * v0.y - v1.x * v1.x - v1.y * v1.y;
#pragma unroll
        for (int o = 16; o; o >>= 1) {
            xr += __shfl_xor_sync(0xffffffffu, xr, o);
            yi += __shfl_xor_sync(0xffffffffu, yi, o);
            zz += __shfl_xor_sync(0xffffffffu, zz, o);
        }
        __syncthreads();
        if ((tid & 31) == 0) {
            redx[tid >> 5] = xr; redy[tid >> 5] = yi; redz[tid >> 5] = zz;
        }
        __syncthreads();
        if (tid < 32) {
            float vx = (tid < 16) ? redx[tid] : 0.f;
            float vy = (tid < 16) ? redy[tid] : 0.f;
            float vz = (tid < 16) ? redz[tid] : 0.f;
#pragma unroll
            for (int o = 8; o; o >>= 1) {
                vx += __shfl_xor_sync(0xffffffffu, vx, o);
                vy += __shfl_xor_sync(0xffffffffu, vy, o);
                vz += __shfl_xor_sync(0xffffffffu, vz, o);
            }
            if (tid == 0) {
                out[b * 30 + w]      = 2.f * vx;
                out[b * 30 + 10 + w] = 2.f * vy;
                out[b * 30 + 20 + w] = vz;
            }
        }
    }
}

// ----------------------------- launch ---------------------------------------
extern "C" void kernel_launch(void* const* d_in, const int* in_sizes, int n_in,
                              void* d_out, int out_size)
{
    const float* tokens = (const float*)d_in[0];  // (128, 32, 512)
    const float* W      = (const float*)d_in[1];  // (40, 512)
    const float* bias   = (const float*)d_in[2];  // (40,)
    const float* lre    = (const float*)d_in[3];  // (32,)
    const float* lim    = (const float*)d_in[4];  // (32,)
    const float* qsvt   = (const float*)d_in[5];  // (3,)
    const float* ffp    = (const float*)d_in[6];  // (40,)
    float* out          = (float*)d_out;          // (128, 30)

    params_kernel<<<NSIM, 256>>>(tokens, W, bias, lre, lim);
    wsim_kernel<true><<<NB * 4, 256>>>();
    wsim_kernel<false><<<NB * 4, 256>>>();
    final_kernel<<<NB, 512>>>(qsvt, ffp, out);
}

// round 14
// speedup vs baseline: 1.6202x; 1.6202x over previous
#include <cuda_runtime.h>
#include <cuda_bf16.h>
#include <math.h>

// Problem constants
#define NQ   10
#define DIM  1024        // 2^NQ
#define NT   32
#define DM   512
#define NB   128         // batch
#define NPQC 40
#define NSIM (NB * NT)   // 4096 statevector sims per pass

typedef unsigned long long ull;

// ---------------- device scratch (static globals, no allocation) -------------
__device__ float2 d_part1[(size_t)NB * 4 * DIM]; // pass-1 per-CTA LCU partials (4 MB)
__device__ float2 d_part2[(size_t)NB * 4 * DIM]; // pass-2 per-CTA LCU partials (4 MB)
__device__ float2 d_gt[(size_t)NSIM * NPQC];     // per-(b,l) gate (cos,sin) tables
__device__ float2 d_lcuW[NT];                    // normalized LCU weights

// Gate encoding: bit0 = type (0=RY, 1=CRX); bits[1..4] = RY bit position or
// CRX control position; bits[5..8] = CRX target position.
// Bit position p of qubit wire w is p = 9 - w (reference is big-endian).
#define RYG(p)      ((unsigned)((p) << 1))
#define CXG(cp, tp) ((unsigned)(1u | ((cp) << 1) | ((tp) << 5)))

#define GATE_LIST                                                              \
        RYG(9), RYG(8), RYG(7), RYG(6), RYG(5), RYG(4), RYG(3), RYG(2),        \
        RYG(1), RYG(0),                                                        \
        CXG(0, 9), CXG(1, 0), CXG(2, 1), CXG(3, 2), CXG(4, 3),                 \
        CXG(5, 4), CXG(6, 5), CXG(7, 6), CXG(8, 7), CXG(9, 8),                 \
        RYG(9), RYG(8), RYG(7), RYG(6), RYG(5), RYG(4), RYG(3), RYG(2),        \
        RYG(1), RYG(0),                                                        \
        CXG(0, 1), CXG(9, 0), CXG(8, 9), CXG(7, 8), CXG(6, 7),                 \
        CXG(5, 6), CXG(4, 5), CXG(3, 4), CXG(2, 3), CXG(1, 2)

// -------- packed f32x2 helpers: SINGLE-instruction asm, no temp blocks -------
__device__ __forceinline__ ull mul2(ull a, ull b) {
    ull d; asm("mul.rn.f32x2 %0,%1,%2;" : "=l"(d) : "l"(a), "l"(b)); return d;
}
__device__ __forceinline__ ull fma2(ull a, ull b, ull c) {
    ull d; asm("fma.rn.f32x2 %0,%1,%2,%3;" : "=l"(d) : "l"(a), "l"(b), "l"(c)); return d;
}
__device__ __forceinline__ ull add2(ull a, ull b) {
    ull d; asm("add.rn.f32x2 %0,%1,%2;" : "=l"(d) : "l"(a), "l"(b)); return d;
}
__device__ __forceinline__ ull pk2(float lo, float hi) {
    ull v; asm("mov.b64 %0, {%1,%2};" : "=l"(v) : "f"(lo), "f"(hi)); return v;
}
__device__ __forceinline__ float lo2(ull v) {
    float f; asm("{ .reg .b32 hi; mov.b64 {%0,hi}, %1; }" : "=f"(f) : "l"(v)); return f;
}
__device__ __forceinline__ float hi2(ull v) {
    float f; asm("{ .reg .b32 lo; mov.b64 {lo,%0}, %1; }" : "=f"(f) : "l"(v)); return f;
}
__device__ __forceinline__ ull swap2(ull v) {
    ull d;
    asm("{ .reg .b32 lo,hi; mov.b64 {lo,hi}, %1; mov.b64 %0, {hi,lo}; }"
        : "=l"(d) : "l"(v));
    return d;
}

// ---- register-resident circuit: lane L slot r holds amplitude g = r*32+L ----
//   g bits 5..9 -> register bits (packed f32x2 butterflies, A[] stays packed)
//   g bits 0..4 -> lane bits (partner via shfl.xor of the two halves)
__device__ __forceinline__ void apply_circuit_reg(ull A[32],
                                                  const float2* __restrict__ g,
                                                  int L)
{
    constexpr unsigned G[NPQC] = { GATE_LIST };
#pragma unroll
    for (int k = 0; k < NPQC; ++k) {
        const unsigned e = G[k];
        const float cth = g[k].x;
        const float sth = g[k].y;
        if (!(e & 1u)) {
            const int p = (int)((e >> 1) & 15u);
            if (p >= 5) {
                // RY on register bit: a0' = c*a0 - s*a1 ; a1' = s*a0 + c*a1
                const int rb = 1 << (p - 5);
                const ull C2 = pk2(cth, cth);
                const ull S2 = pk2(sth, sth);
                const ull N2 = pk2(-sth, -sth);
#pragma unroll
                for (int r0 = 0; r0 < 32; ++r0) {
                    if (!(r0 & rb)) {
                        const int r1 = r0 | rb;
                        const ull t0 = fma2(N2, A[r1], mul2(C2, A[r0]));
                        const ull t1 = fma2(C2, A[r1], mul2(S2, A[r0]));
                        A[r0] = t0; A[r1] = t1;
                    }
                }
            } else {
                // RY on lane bit: a' = c*a + se*partner (se carries sign)
                const int lb = 1 << p;
                const float se = (L & lb) ? sth : -sth;
                const ull C2  = pk2(cth, cth);
                const ull SE2 = pk2(se, se);
#pragma unroll
                for (int r = 0; r < 32; ++r) {
                    const float px = __shfl_xor_sync(0xffffffffu, lo2(A[r]), lb);
                    const float py = __shfl_xor_sync(0xffffffffu, hi2(A[r]), lb);
                    A[r] = fma2(SE2, pk2(px, py), mul2(C2, A[r]));
                }
            }
        } else {
            const int cp = (int)((e >> 1) & 15u);
            const int tp = (int)((e >> 5) & 15u);
            if (tp >= 5) {
                // CRX butterfly on register bit:
                // a0' = C2*A + (s,-s)*swap(B) ; a1' = C2*B + (s,-s)*swap(A)
                const int rb = 1 << (tp - 5);
                if (cp >= 5) {
                    const int cb = 1 << (cp - 5);
                    const ull C2  = pk2(cth, cth);
                    const ull SPM = pk2(sth, -sth);
#pragma unroll
                    for (int r0 = 0; r0 < 32; ++r0) {
                        if (!(r0 & rb) && (r0 & cb)) {
                            const int r1 = r0 | rb;
                            const ull t0 = fma2(SPM, swap2(A[r1]), mul2(C2, A[r0]));
                            const ull t1 = fma2(SPM, swap2(A[r0]), mul2(C2, A[r1]));
                            A[r0] = t0; A[r1] = t1;
                        }
                    }
                } else {
                    // lane-bit control folded into coefficients
                    const bool act = (L >> cp) & 1;
                    const float ce = act ? cth : 1.f;
                    const float se = act ? sth : 0.f;
                    const ull C2  = pk2(ce, ce);
                    const ull SPM = pk2(se, -se);
#pragma unroll
                    for (int r0 = 0; r0 < 32; ++r0) {
                        if (!(r0 & rb)) {
                            const int r1 = r0 | rb;
                            const ull t0 = fma2(SPM, swap2(A[r1]), mul2(C2, A[r0]));
                            const ull t1 = fma2(SPM, swap2(A[r0]), mul2(C2, A[r1]));
                            A[r0] = t0; A[r1] = t1;
                        }
                    }
                }
            } else {
                // RX on lane bit: a' = C2*A + (s,-s)*(py,px)  (pre-swapped pack)
                const int lb = 1 << tp;
                if (cp >= 5) {
                    const int cb = 1 << (cp - 5);
                    const ull C2  = pk2(cth, cth);
                    const ull SPM = pk2(sth, -sth);
#pragma unroll
                    for (int r = 0; r < 32; ++r) {
                        if (r & cb) {
                            const float px = __shfl_xor_sync(0xffffffffu, lo2(A[r]), lb);
                            const float py = __shfl_xor_sync(0xffffffffu, hi2(A[r]), lb);
                            A[r] = fma2(SPM, pk2(py, px), mul2(C2, A[r]));
                        }
                    }
                } else {
                    const bool act = (L >> cp) & 1;
                    const float ce = act ? cth : 1.f;
                    const float se = act ? sth : 0.f;
                    const ull C2  = pk2(ce, ce);
                    const ull SPM = pk2(se, -se);
#pragma unroll
                    for (int r = 0; r < 32; ++r) {
                        const float px = __shfl_xor_sync(0xffffffffu, lo2(A[r]), lb);
                        const float py = __shfl_xor_sync(0xffffffffu, hi2(A[r]), lb);
                        A[r] = fma2(SPM, pk2(py, px), mul2(C2, A[r]));
                    }
                }
            }
        }
    }
}

// ----------------------------- kernels --------------------------------------

// pqc_params = tokens @ W.T + b -> (cos, sin) of theta/2 per gate.
// One block per (b,l) row; 256 threads; float4-vectorized dots. (R7-verified.)
// Block 0 additionally computes the normalized LCU weights (warp 0).
__global__ void params_kernel(const float* __restrict__ tokens,
                              const float* __restrict__ W,
                              const float* __restrict__ bias,
                              const float* __restrict__ lre,
                              const float* __restrict__ lim)
{
    const int blk = blockIdx.x;                 // b*32 + l
    const int tid = threadIdx.x;

    if (blk == 0 && tid < 32) {
        const float r = lre[tid], i = lim[tid];
        const float a = sqrtf(r * r + i * i);
        float ssum = a;
#pragma unroll
        for (int o = 16; o; o >>= 1) ssum += __shfl_xor_sync(0xffffffffu, ssum, o);
        d_lcuW[tid] = make_float2(r / ssum, i / ssum);
    }

    __shared__ float4 sh4[DM / 4];              // 128 float4 = 512 floats
    const float4* row4 = (const float4*)(tokens + (size_t)blk * DM);
    if (tid < DM / 4) sh4[tid] = row4[tid];
    __syncthreads();

    const int warp = tid >> 5;
    const int lane = tid & 31;
    for (int k = warp; k < NPQC; k += 8) {
        const float4* w4 = (const float4*)(W + (size_t)k * DM);
        float acc = 0.f;
#pragma unroll
        for (int j = 0; j < 4; ++j) {
            const int idx = lane + j * 32;
            const float4 t = sh4[idx];
            const float4 ww = __ldg(w4 + idx);
            acc += t.x * ww.x + t.y * ww.y + t.z * ww.z + t.w * ww.w;
        }
#pragma unroll
        for (int o = 16; o; o >>= 1) acc += __shfl_xor_sync(0xffffffffu, acc, o);
        if (lane == 0) {
            const float h = 0.5f * (acc + __ldg(bias + k));
            d_gt[(size_t)blk * NPQC + k] = make_float2(cosf(h), sinf(h));
        }
    }
}

// Warp-per-statevector simulator; amplitudes packed as f32x2 (ull).
// One CTA = 8 warps = 8 consecutive l-values of one batch. Pass 2 rebuilds the
// monomial state from the 4 pass-1 partials (smem-staged, summed once per CTA).
// LCU-weighted sum over the CTA's 8 l's is reduced in smem -> pass partials.
template <bool FIRST>
__global__ void __launch_bounds__(256, 2) wsim_kernel()
{
    const int blk = blockIdx.x;          // b*4 + c
    const int b   = blk >> 2;
    const int c   = blk & 3;
    const int tid = threadIdx.x;         // 256
    const int w   = tid >> 5;            // warp 0..7
    const int L   = tid & 31;
    const int l   = c * 8 + w;

    __shared__ float2 sg[8][NPQC];       // gate tables (2.5 KB)
    __shared__ ull    sbuf[4][DIM];      // staging / reduction slots (32 KB)

    // Load 8 gate tables (contiguous in d_gt) cooperatively.
    {
        const float2* gbase = d_gt + ((size_t)(b * NT + c * 8)) * NPQC;
        for (int i = tid; i < 8 * NPQC; i += 256)
            (&sg[0][0])[i] = gbase[i];
    }

    if (!FIRST) {
        // mono = sum of the batch's 4 pass-1 partials; stage in sbuf[0].
        const ull* p1 = (const ull*)d_part1;
        for (int g = tid; g < DIM; g += 256) {
            ull m = p1[(size_t)(b * 4 + 0) * DIM + g];
#pragma unroll
            for (int cc = 1; cc < 4; ++cc)
                m = add2(m, p1[(size_t)(b * 4 + cc) * DIM + g]);
            sbuf[0][g] = m;
        }
    }
    __syncthreads();

    ull A[32];
    if (FIRST) {
#pragma unroll
        for (int r = 0; r < 32; ++r) A[r] = 0ull;
        if (L == 0) A[0] = pk2(1.f, 0.f);
    } else {
#pragma unroll
        for (int r = 0; r < 32; ++r) A[r] = sbuf[0][r * 32 + L];
    }
    __syncthreads();   // sbuf[0] reads complete before epilogue reuses sbuf

    apply_circuit_reg(A, sg[w], L);

    // ---- LCU weight + in-CTA reduction over the 8 warps --------------------
    // a' = (wx*vx - wy*vy, wx*vy + wy*vx) = WX2*V + (-wy,wy)*swap(V)
    {
        const float2 wl = d_lcuW[l];
        const ull WX2 = pk2(wl.x, wl.x);
        const ull WYM = pk2(-wl.y, wl.y);
#pragma unroll
        for (int r = 0; r < 32; ++r)
            A[r] = fma2(WYM, swap2(A[r]), mul2(WX2, A[r]));
    }
    // stage 1: warps 0-3 write their weighted state to slot w
    if (w < 4) {
#pragma unroll
        for (int r = 0; r < 32; ++r) sbuf[w][r * 32 + L] = A[r];
    }
    __syncthreads();
    // stage 2: warps 4-7 add into slot w-4
    if (w >= 4) {
        const int slot = w - 4;
#pragma unroll
        for (int r = 0; r < 32; ++r)
            sbuf[slot][r * 32 + L] = add2(sbuf[slot][r * 32 + L], A[r]);
    }
    __syncthreads();
    // stage 3: 256 threads reduce the 4 slots, write the CTA partial
    ull* outp = (ull*)(FIRST ? d_part1 : d_part2) + (size_t)blk * DIM;
#pragma unroll
    for (int j = 0; j < 4; ++j) {
        const int g = tid + j * 256;
        ull m = sbuf[0][g];
#pragma unroll
        for (int wi = 1; wi < 4; ++wi) m = add2(m, sbuf[wi][g]);
        outp[g] = m;
    }
}

// -------- shared-memory circuit (used only by final_kernel, 128 CTAs) -------
__device__ __forceinline__ void apply_circuit_smem(float2* s, const float2* g, int tid)
{
    const unsigned G[NPQC] = { GATE_LIST };
#pragma unroll
    for (int k = 0; k < NPQC; ++k) {
        const unsigned e = G[k];
        const float c  = g[k].x;
        const float sn = g[k].y;
        if (!(e & 1u)) {
            const int p   = (int)((e >> 1) & 15u);
            const int bit = 1 << p;
            const int low = tid & (bit - 1);
            const int i0  = ((tid >> p) << (p + 1)) | low;
            const int i1  = i0 | bit;
            const float2 a0 = s[i0];
            const float2 a1 = s[i1];
            s[i0] = make_float2(c * a0.x - sn * a1.x, c * a0.y - sn * a1.y);
            s[i1] = make_float2(sn * a0.x + c * a1.x, sn * a0.y + c * a1.y);
        } else if (tid < 256) {
            const int cp = (int)((e >> 1) & 15u);
            const int tp = (int)((e >> 5) & 15u);
            const int pl = (cp < tp) ? cp : tp;
            const int ph = cp ^ tp ^ pl;
            const int bl = 1 << pl;
            const int bh = 1 << ph;
            const int low1 = tid & (bl - 1);
            const int t1   = ((tid >> pl) << (pl + 1)) | low1;
            const int low2 = t1 & (bh - 1);
            const int idx  = ((t1 >> ph) << (ph + 1)) | low2;
            const int i0   = idx | (1 << cp);
            const int i1   = i0 | (1 << tp);
            const float2 a0 = s[i0];
            const float2 a1 = s[i1];
            s[i0] = make_float2(c * a0.x + sn * a1.y, c * a0.y - sn * a1.x);
            s[i1] = make_float2(sn * a0.y + c * a1.x, c * a1.y - sn * a0.x);
        }
        __syncthreads();
    }
}

// Build QSVT accumulator from the 8 partials, normalize, apply feed-forward
// ansatz, measure X/Y/Z on all 10 wires. (R7-verified smem version.)
__global__ void __launch_bounds__(512) final_kernel(const float* __restrict__ qsvt,
                                                    const float* __restrict__ ffp,
                                                    float* __restrict__ out)
{
    const int b   = blockIdx.x;
    const int tid = threadIdx.x;         // 512

    __shared__ float2 s[DIM];
    __shared__ float2 g[NPQC];
    __shared__ float redx[16], redy[16], redz[16];

    const float c0 = qsvt[0], c1 = qsvt[1], c2 = qsvt[2];

    float2 a0, a1;
    {
        float2 m1a = make_float2(0.f, 0.f), m2a = make_float2(0.f, 0.f);
        float2 m1b = make_float2(0.f, 0.f), m2b = make_float2(0.f, 0.f);
#pragma unroll
        for (int c = 0; c < 4; ++c) {
            const size_t base = (size_t)(b * 4 + c) * DIM;
            float2 v;
            v = d_part1[base + tid];       m1a.x += v.x; m1a.y += v.y;
            v = d_part2[base + tid];       m2a.x += v.x; m2a.y += v.y;
            v = d_part1[base + tid + 512]; m1b.x += v.x; m1b.y += v.y;
            v = d_part2[base + tid + 512]; m2b.x += v.x; m2b.y += v.y;
        }
        a0 = make_float2(c1 * m1a.x + c2 * m2a.x + (tid == 0 ? c0 : 0.f),
                         c1 * m1a.y + c2 * m2a.y);
        a1 = make_float2(c1 * m1b.x + c2 * m2b.x,
                         c1 * m1b.y + c2 * m2b.y);
    }

    if (tid < NPQC) {
        const float h = 0.5f * ffp[tid];
        g[tid] = make_float2(cosf(h), sinf(h));
    }

    // L2 norm (constant QSVT scale cancels in normalization)
    float nn = a0.x * a0.x + a0.y * a0.y + a1.x * a1.x + a1.y * a1.y;
#pragma unroll
    for (int o = 16; o; o >>= 1) nn += __shfl_xor_sync(0xffffffffu, nn, o);
    if ((tid & 31) == 0) redx[tid >> 5] = nn;
    __syncthreads();
    if (tid < 32) {
        float v = (tid < 16) ? redx[tid] : 0.f;
#pragma unroll
        for (int o = 8; o; o >>= 1) v += __shfl_xor_sync(0xffffffffu, v, o);
        if (tid == 0) redx[0] = rsqrtf(v);
    }
    __syncthreads();
    const float sc = redx[0];
    s[tid]       = make_float2(a0.x * sc, a0.y * sc);
    s[tid + 512] = make_float2(a1.x * sc, a1.y * sc);
    __syncthreads();

    apply_circuit_smem(s, g, tid);

    // measurement: per wire w, pairs split on bit p = 9-w
#pragma unroll
    for (int w = 0; w < NQ; ++w) {
        const int p   = 9 - w;
        const int bit = 1 << p;
        const int low = tid & (bit - 1);
        const int i0  = ((tid >> p) << (p + 1)) | low;
        const int i1  = i0 | bit;
        const float2 v0 = s[i0];
        const float2 v1 = s[i1];
        float xr = v0.x * v1.x + v0.y * v1.y;             // Re(conj(a0)*a1)
        float yi = v0.x * v1.y - v0.y * v1.x;             // Im(conj(a0)*a1)
        float zz = v0.x * v0.x + v0.y * v0.y - v1.x * v1.x - v1.y * v1.y;
#pragma unroll
        for (int o = 16; o; o >>= 1) {
            xr += __shfl_xor_sync(0xffffffffu, xr, o);
            yi += __shfl_xor_sync(0xffffffffu, yi, o);
            zz += __shfl_xor_sync(0xffffffffu, zz, o);
        }
        __syncthreads();
        if ((tid & 31) == 0) {
            redx[tid >> 5] = xr; redy[tid >> 5] = yi; redz[tid >> 5] = zz;
        }
        __syncthreads();
        if (tid < 32) {
            float vx = (tid < 16) ? redx[tid] : 0.f;
            float vy = (tid < 16) ? redy[tid] : 0.f;
            float vz = (tid < 16) ? redz[tid] : 0.f;
#pragma unroll
            for (int o = 8; o; o >>= 1) {
                vx += __shfl_xor_sync(0xffffffffu, vx, o);
                vy += __shfl_xor_sync(0xffffffffu, vy, o);
                vz += __shfl_xor_sync(0xffffffffu, vz, o);
            }
            if (tid == 0) {
                out[b * 30 + w]      = 2.f * vx;
                out[b * 30 + 10 + w] = 2.f * vy;
                out[b * 30 + 20 + w] = vz;
            }
        }
    }
}

// ----------------------------- launch ---------------------------------------
extern "C" void kernel_launch(void* const* d_in, const int* in_sizes, int n_in,
                              void* d_out, int out_size)
{
    const float* tokens = (const float*)d_in[0];  // (128, 32, 512)
    const float* W      = (const float*)d_in[1];  // (40, 512)
    const float* bias   = (const float*)d_in[2];  // (40,)
    const float* lre    = (const float*)d_in[3];  // (32,)
    const float* lim    = (const float*)d_in[4];  // (32,)
    const float* qsvt   = (const float*)d_in[5];  // (3,)
    const float* ffp    = (const float*)d_in[6];  // (40,)
    float* out          = (float*)d_out;          // (128, 30)

    params_kernel<<<NSIM, 256>>>(tokens, W, bias, lre, lim);
    wsim_kernel<true><<<NB * 4, 256>>>();
    wsim_kernel<false><<<NB * 4, 256>>>();
    final_kernel<<<NB, 512>>>(qsvt, ffp, out);
}

// round 16
// speedup vs baseline: 1.8646x; 1.1508x over previous
#include <cuda_runtime.h>
#include <cuda_bf16.h>
#include <math.h>

// Problem constants
#define NQ   10
#define DIM  1024        // 2^NQ
#define NT   32
#define DM   512
#define NB   128         // batch
#define NPQC 40
#define NSIM (NB * NT)   // 4096 statevector sims per pass

typedef unsigned long long ull;

// ---------------- device scratch (static globals, no allocation) -------------
__device__ float2 d_part1[(size_t)NB * 4 * DIM]; // pass-1 per-CTA LCU partials (4 MB)
__device__ float2 d_part2[(size_t)NB * 4 * DIM]; // pass-2 per-CTA LCU partials (4 MB)
__device__ float2 d_gt[(size_t)NSIM * NPQC];     // per-(b,l) gate (cos,sin) tables

// Gate encoding: bit0 = type (0=RY, 1=CRX); bits[1..4] = RY bit position or
// CRX control position; bits[5..8] = CRX target position.
// Bit position p of qubit wire w is p = 9 - w (reference is big-endian).
#define RYG(p)      ((unsigned)((p) << 1))
#define CXG(cp, tp) ((unsigned)(1u | ((cp) << 1) | ((tp) << 5)))

#define GATE_LIST                                                              \
        RYG(9), RYG(8), RYG(7), RYG(6), RYG(5), RYG(4), RYG(3), RYG(2),        \
        RYG(1), RYG(0),                                                        \
        CXG(0, 9), CXG(1, 0), CXG(2, 1), CXG(3, 2), CXG(4, 3),                 \
        CXG(5, 4), CXG(6, 5), CXG(7, 6), CXG(8, 7), CXG(9, 8),                 \
        RYG(9), RYG(8), RYG(7), RYG(6), RYG(5), RYG(4), RYG(3), RYG(2),        \
        RYG(1), RYG(0),                                                        \
        CXG(0, 1), CXG(9, 0), CXG(8, 9), CXG(7, 8), CXG(6, 7),                 \
        CXG(5, 6), CXG(4, 5), CXG(3, 4), CXG(2, 3), CXG(1, 2)

// -------- packed f32x2 helpers: SINGLE-instruction asm, no temp blocks -------
__device__ __forceinline__ ull mul2(ull a, ull b) {
    ull d; asm("mul.rn.f32x2 %0,%1,%2;" : "=l"(d) : "l"(a), "l"(b)); return d;
}
__device__ __forceinline__ ull fma2(ull a, ull b, ull c) {
    ull d; asm("fma.rn.f32x2 %0,%1,%2,%3;" : "=l"(d) : "l"(a), "l"(b), "l"(c)); return d;
}
__device__ __forceinline__ ull add2(ull a, ull b) {
    ull d; asm("add.rn.f32x2 %0,%1,%2;" : "=l"(d) : "l"(a), "l"(b)); return d;
}
__device__ __forceinline__ ull pk2(float lo, float hi) {
    ull v; asm("mov.b64 %0, {%1,%2};" : "=l"(v) : "f"(lo), "f"(hi)); return v;
}
__device__ __forceinline__ float lo2(ull v) {
    float f; asm("{ .reg .b32 hi; mov.b64 {%0,hi}, %1; }" : "=f"(f) : "l"(v)); return f;
}
__device__ __forceinline__ float hi2(ull v) {
    float f; asm("{ .reg .b32 lo; mov.b64 {lo,%0}, %1; }" : "=f"(f) : "l"(v)); return f;
}
__device__ __forceinline__ ull swap2(ull v) {
    ull d;
    asm("{ .reg .b32 lo,hi; mov.b64 {lo,hi}, %1; mov.b64 %0, {hi,lo}; }"
        : "=l"(d) : "l"(v));
    return d;
}

// ---- register-resident circuit: lane L slot r holds amplitude g = r*32+L ----
//   g bits 5..9 -> register bits (packed f32x2 butterflies, A[] stays packed)
//   g bits 0..4 -> lane bits (partner via shfl.xor of the two halves)
// START: first gate index (pass 1 skips the opening RY layer, handled by the
// product-state init).
template <int START>
__device__ __forceinline__ void apply_circuit_reg(ull A[32],
                                                  const float2* __restrict__ g,
                                                  int L)
{
    constexpr unsigned G[NPQC] = { GATE_LIST };
#pragma unroll
    for (int k = START; k < NPQC; ++k) {
        const unsigned e = G[k];
        const float cth = g[k].x;
        const float sth = g[k].y;
        if (!(e & 1u)) {
            const int p = (int)((e >> 1) & 15u);
            if (p >= 5) {
                // RY on register bit: a0' = c*a0 - s*a1 ; a1' = s*a0 + c*a1
                const int rb = 1 << (p - 5);
                const ull C2 = pk2(cth, cth);
                const ull S2 = pk2(sth, sth);
                const ull N2 = pk2(-sth, -sth);
#pragma unroll
                for (int r0 = 0; r0 < 32; ++r0) {
                    if (!(r0 & rb)) {
                        const int r1 = r0 | rb;
                        const ull t0 = fma2(N2, A[r1], mul2(C2, A[r0]));
                        const ull t1 = fma2(C2, A[r1], mul2(S2, A[r0]));
                        A[r0] = t0; A[r1] = t1;
                    }
                }
            } else {
                // RY on lane bit: a' = c*a + se*partner (se carries sign)
                const int lb = 1 << p;
                const float se = (L & lb) ? sth : -sth;
                const ull C2  = pk2(cth, cth);
                const ull SE2 = pk2(se, se);
#pragma unroll
                for (int r = 0; r < 32; ++r) {
                    const float px = __shfl_xor_sync(0xffffffffu, lo2(A[r]), lb);
                    const float py = __shfl_xor_sync(0xffffffffu, hi2(A[r]), lb);
                    A[r] = fma2(SE2, pk2(px, py), mul2(C2, A[r]));
                }
            }
        } else {
            const int cp = (int)((e >> 1) & 15u);
            const int tp = (int)((e >> 5) & 15u);
            if (tp >= 5) {
                // CRX butterfly on register bit:
                // a0' = C2*A + (s,-s)*swap(B) ; a1' = C2*B + (s,-s)*swap(A)
                const int rb = 1 << (tp - 5);
                if (cp >= 5) {
                    const int cb = 1 << (cp - 5);
                    const ull C2  = pk2(cth, cth);
                    const ull SPM = pk2(sth, -sth);
#pragma unroll
                    for (int r0 = 0; r0 < 32; ++r0) {
                        if (!(r0 & rb) && (r0 & cb)) {
                            const int r1 = r0 | rb;
                            const ull t0 = fma2(SPM, swap2(A[r1]), mul2(C2, A[r0]));
                            const ull t1 = fma2(SPM, swap2(A[r0]), mul2(C2, A[r1]));
                            A[r0] = t0; A[r1] = t1;
                        }
                    }
                } else {
                    // lane-bit control folded into coefficients
                    const bool act = (L >> cp) & 1;
                    const float ce = act ? cth : 1.f;
                    const float se = act ? sth : 0.f;
                    const ull C2  = pk2(ce, ce);
                    const ull SPM = pk2(se, -se);
#pragma unroll
                    for (int r0 = 0; r0 < 32; ++r0) {
                        if (!(r0 & rb)) {
                            const int r1 = r0 | rb;
                            const ull t0 = fma2(SPM, swap2(A[r1]), mul2(C2, A[r0]));
                            const ull t1 = fma2(SPM, swap2(A[r0]), mul2(C2, A[r1]));
                            A[r0] = t0; A[r1] = t1;
                        }
                    }
                }
            } else {
                // RX on lane bit: a' = C2*A + (s,-s)*(py,px)  (pre-swapped pack)
                const int lb = 1 << tp;
                if (cp >= 5) {
                    const int cb = 1 << (cp - 5);
                    const ull C2  = pk2(cth, cth);
                    const ull SPM = pk2(sth, -sth);
#pragma unroll
                    for (int r = 0; r < 32; ++r) {
                        if (r & cb) {
                            const float px = __shfl_xor_sync(0xffffffffu, lo2(A[r]), lb);
                            const float py = __shfl_xor_sync(0xffffffffu, hi2(A[r]), lb);
                            A[r] = fma2(SPM, pk2(py, px), mul2(C2, A[r]));
                        }
                    }
                } else {
                    const bool act = (L >> cp) & 1;
                    const float ce = act ? cth : 1.f;
                    const float se = act ? sth : 0.f;
                    const ull C2  = pk2(ce, ce);
                    const ull SPM = pk2(se, -se);
#pragma unroll
                    for (int r = 0; r < 32; ++r) {
                        const float px = __shfl_xor_sync(0xffffffffu, lo2(A[r]), lb);
                        const float py = __shfl_xor_sync(0xffffffffu, hi2(A[r]), lb);
                        A[r] = fma2(SPM, pk2(py, px), mul2(C2, A[r]));
                    }
                }
            }
        }
    }
}

// Per-warp normalized LCU weight for token l: (lre[l], lim[l]) / sum|lcu|.
__device__ __forceinline__ float2 lcu_weight(const float* __restrict__ lre,
                                             const float* __restrict__ lim,
                                             int L, int l)
{
    const float rr = __ldg(lre + L);
    const float ii = __ldg(lim + L);
    float ssum = sqrtf(rr * rr + ii * ii);
#pragma unroll
    for (int o = 16; o; o >>= 1) ssum += __shfl_xor_sync(0xffffffffu, ssum, o);
    const float wx = __shfl_sync(0xffffffffu, rr, l) / ssum;
    const float wy = __shfl_sync(0xffffffffu, ii, l) / ssum;
    return make_float2(wx, wy);
}

// ----------------------------- kernels --------------------------------------

// Warp-per-statevector simulator; amplitudes packed as f32x2 (ull).
// One CTA = 8 warps = 8 consecutive l-values of one batch.
// Pass 1 (FIRST): fuses the params GEMM — stages its 8 token rows in smem,
// warps cooperatively compute the 8x40 thetas (W read once per CTA: 40 MB
// total L2 traffic vs 320 MB for the standalone kernel), distributed sincos,
// writes d_gt for pass 2, and starts from the |0> product state (skipping the
// opening RY layer).
// Pass 2: rebuilds mono from the 4 pass-1 partials, loads gate tables from
// d_gt. Both passes reduce the LCU-weighted sum over their 8 l's in smem.
template <bool FIRST>
__global__ void __launch_bounds__(256, 2) wsim_kernel(
    const float* __restrict__ tokens,
    const float* __restrict__ W,
    const float* __restrict__ bias,
    const float* __restrict__ lre,
    const float* __restrict__ lim)
{
    const int blk = blockIdx.x;          // b*4 + c
    const int b   = blk >> 2;
    const int c   = blk & 3;
    const int tid = threadIdx.x;         // 256
    const int w   = tid >> 5;            // warp 0..7
    const int L   = tid & 31;
    const int l   = c * 8 + w;

    __shared__ float2 sg[8][NPQC];       // gate tables (2.5 KB)
    __shared__ ull    sbuf[4][DIM];      // staging / reduction slots (32 KB)
    __shared__ float  th[8][NPQC];       // raw thetas (pass 1 only, 1.25 KB)

    if (FIRST) {
        // ---- Phase A: stage this CTA's 8 token rows into smem --------------
        float* tok_s = (float*)sbuf;     // 8 x 512 floats = 16 KB
        {
            const float4* t4 = (const float4*)(tokens + (size_t)(b * NT + c * 8) * DM);
            float4* d4 = (float4*)tok_s;
            for (int i = tid; i < 8 * (DM / 4); i += 256)
                d4[i] = t4[i];
        }
        __syncthreads();

        // ---- Phase B: warp w computes k = w*5 .. w*5+4 for all 8 rows ------
#pragma unroll
        for (int kk = 0; kk < 5; ++kk) {
            const int k = w * 5 + kk;
            float4 wv[4];
            const float4* w4 = (const float4*)(W + (size_t)k * DM);
#pragma unroll
            for (int j = 0; j < 4; ++j) wv[j] = __ldg(w4 + L + j * 32);
            const float bk = __ldg(bias + k);
#pragma unroll
            for (int row = 0; row < 8; ++row) {
                const float4* tr = (const float4*)(tok_s + row * DM);
                float acc = 0.f;
#pragma unroll
                for (int j = 0; j < 4; ++j) {
                    const float4 t = tr[L + j * 32];
                    const float4 ww = wv[j];
                    acc += t.x * ww.x + t.y * ww.y + t.z * ww.z + t.w * ww.w;
                }
#pragma unroll
                for (int o = 16; o; o >>= 1) acc += __shfl_xor_sync(0xffffffffu, acc, o);
                if (L == row) th[row][k] = acc + bk;
            }
        }
        __syncthreads();

        // ---- Phase C: distributed sincos; fill sg + d_gt -------------------
        for (int i = tid; i < 8 * NPQC; i += 256) {
            const int row = i / NPQC;
            const int k   = i - row * NPQC;
            float sv, cv;
            __sincosf(0.5f * th[row][k], &sv, &cv);
            const float2 gcs = make_float2(cv, sv);
            sg[row][k] = gcs;
            d_gt[(size_t)(b * NT + c * 8 + row) * NPQC + k] = gcs;
        }
        __syncthreads();
    } else {
        // Load 8 gate tables (contiguous in d_gt) cooperatively.
        const float2* gbase = d_gt + ((size_t)(b * NT + c * 8)) * NPQC;
        for (int i = tid; i < 8 * NPQC; i += 256)
            (&sg[0][0])[i] = gbase[i];

        // mono = sum of the batch's 4 pass-1 partials; stage in sbuf[0].
        const ull* p1 = (const ull*)d_part1;
        for (int g = tid; g < DIM; g += 256) {
            ull m = p1[(size_t)(b * 4 + 0) * DIM + g];
#pragma unroll
            for (int cc = 1; cc < 4; ++cc)
                m = add2(m, p1[(size_t)(b * 4 + cc) * DIM + g]);
            sbuf[0][g] = m;
        }
        __syncthreads();
    }

    ull A[32];
    if (FIRST) {
        // Product state after the opening RY layer on |0...0>:
        // amp(g) = prod_p (bit_p(g) ? sin(h_{9-p}) : cos(h_{9-p})), all real.
        float cf = 1.f;
#pragma unroll
        for (int p = 0; p < 5; ++p) {
            const float2 gk = sg[w][9 - p];
            cf *= ((L >> p) & 1) ? gk.y : gk.x;
        }
        float f[32];
        f[0] = cf;
        int n = 1;
#pragma unroll
        for (int j = 0; j < 5; ++j) {
            const float2 gk = sg[w][4 - j];    // position p = 5+j -> gate 9-p
#pragma unroll
            for (int i = 0; i < 16; ++i) {
                if (i < n) {
                    f[n + i] = f[i] * gk.y;
                    f[i]     = f[i] * gk.x;
                }
            }
            n *= 2;
        }
#pragma unroll
        for (int r = 0; r < 32; ++r) A[r] = pk2(f[r], 0.f);
    } else {
#pragma unroll
        for (int r = 0; r < 32; ++r) A[r] = sbuf[0][r * 32 + L];
        __syncthreads();   // sbuf[0] reads complete before epilogue reuses sbuf
    }
    if (FIRST) __syncthreads();   // tok_s reads done; sbuf free for epilogue

    apply_circuit_reg<FIRST ? NQ : 0>(A, sg[w], L);

    // ---- LCU weight + in-CTA reduction over the 8 warps --------------------
    // a' = (wx*vx - wy*vy, wx*vy + wy*vx) = WX2*V + (-wy,wy)*swap(V)
    {
        const float2 wl = lcu_weight(lre, lim, L, l);
        const ull WX2 = pk2(wl.x, wl.x);
        const ull WYM = pk2(-wl.y, wl.y);
#pragma unroll
        for (int r = 0; r < 32; ++r)
            A[r] = fma2(WYM, swap2(A[r]), mul2(WX2, A[r]));
    }
    // stage 1: warps 0-3 write their weighted state to slot w
    if (w < 4) {
#pragma unroll
        for (int r = 0; r < 32; ++r) sbuf[w][r * 32 + L] = A[r];
    }
    __syncthreads();
    // stage 2: warps 4-7 add into slot w-4
    if (w >= 4) {
        const int slot = w - 4;
#pragma unroll
        for (int r = 0; r < 32; ++r)
            sbuf[slot][r * 32 + L] = add2(sbuf[slot][r * 32 + L], A[r]);
    }
    __syncthreads();
    // stage 3: 256 threads reduce the 4 slots, write the CTA partial
    ull* outp = (ull*)(FIRST ? d_part1 : d_part2) + (size_t)blk * DIM;
#pragma unroll
    for (int j = 0; j < 4; ++j) {
        const int g = tid + j * 256;
        ull m = sbuf[0][g];
#pragma unroll
        for (int wi = 1; wi < 4; ++wi) m = add2(m, sbuf[wi][g]);
        outp[g] = m;
    }
}

// -------- shared-memory circuit (used only by final_kernel, 128 CTAs) -------
__device__ __forceinline__ void apply_circuit_smem(float2* s, const float2* g, int tid)
{
    const unsigned G[NPQC] = { GATE_LIST };
#pragma unroll
    for (int k = 0; k < NPQC; ++k) {
        const unsigned e = G[k];
        const float c  = g[k].x;
        const float sn = g[k].y;
        if (!(e & 1u)) {
            const int p   = (int)((e >> 1) & 15u);
            const int bit = 1 << p;
            const int low = tid & (bit - 1);
            const int i0  = ((tid >> p) << (p + 1)) | low;
            const int i1  = i0 | bit;
            const float2 a0 = s[i0];
            const float2 a1 = s[i1];
            s[i0] = make_float2(c * a0.x - sn * a1.x, c * a0.y - sn * a1.y);
            s[i1] = make_float2(sn * a0.x + c * a1.x, sn * a0.y + c * a1.y);
        } else if (tid < 256) {
            const int cp = (int)((e >> 1) & 15u);
            const int tp = (int)((e >> 5) & 15u);
            const int pl = (cp < tp) ? cp : tp;
            const int ph = cp ^ tp ^ pl;
            const int bl = 1 << pl;
            const int bh = 1 << ph;
            const int low1 = tid & (bl - 1);
            const int t1   = ((tid >> pl) << (pl + 1)) | low1;
            const int low2 = t1 & (bh - 1);
            const int idx  = ((t1 >> ph) << (ph + 1)) | low2;
            const int i0   = idx | (1 << cp);
            const int i1   = i0 | (1 << tp);
            const float2 a0 = s[i0];
            const float2 a1 = s[i1];
            s[i0] = make_float2(c * a0.x + sn * a1.y, c * a0.y - sn * a1.x);
            s[i1] = make_float2(sn * a0.y + c * a1.x, c * a1.y - sn * a0.x);
        }
        __syncthreads();
    }
}

// Build QSVT accumulator from the 8 partials, normalize, apply feed-forward
// ansatz, measure X/Y/Z on all 10 wires. (R7-verified smem version.)
__global__ void __launch_bounds__(512) final_kernel(const float* __restrict__ qsvt,
                                                    const float* __restrict__ ffp,
                                                    float* __restrict__ out)
{
    const int b   = blockIdx.x;
    const int tid = threadIdx.x;         // 512

    __shared__ float2 s[DIM];
    __shared__ float2 g[NPQC];
    __shared__ float redx[16], redy[16], redz[16];

    const float c0 = qsvt[0], c1 = qsvt[1], c2 = qsvt[2];

    float2 a0, a1;
    {
        float2 m1a = make_float2(0.f, 0.f), m2a = make_float2(0.f, 0.f);
        float2 m1b = make_float2(0.f, 0.f), m2b = make_float2(0.f, 0.f);
#pragma unroll
        for (int c = 0; c < 4; ++c) {
            const size_t base = (size_t)(b * 4 + c) * DIM;
            float2 v;
            v = d_part1[base + tid];       m1a.x += v.x; m1a.y += v.y;
            v = d_part2[base + tid];       m2a.x += v.x; m2a.y += v.y;
            v = d_part1[base + tid + 512]; m1b.x += v.x; m1b.y += v.y;
            v = d_part2[base + tid + 512]; m2b.x += v.x; m2b.y += v.y;
        }
        a0 = make_float2(c1 * m1a.x + c2 * m2a.x + (tid == 0 ? c0 : 0.f),
                         c1 * m1a.y + c2 * m2a.y);
        a1 = make_float2(c1 * m1b.x + c2 * m2b.x,
                         c1 * m1b.y + c2 * m2b.y);
    }

    if (tid < NPQC) {
        const float h = 0.5f * ffp[tid];
        g[tid] = make_float2(cosf(h), sinf(h));
    }

    // L2 norm (constant QSVT scale cancels in normalization)
    float nn = a0.x * a0.x + a0.y * a0.y + a1.x * a1.x + a1.y * a1.y;
#pragma unroll
    for (int o = 16; o; o >>= 1) nn += __shfl_xor_sync(0xffffffffu, nn, o);
    if ((tid & 31) == 0) redx[tid >> 5] = nn;
    __syncthreads();
    if (tid < 32) {
        float v = (tid < 16) ? redx[tid] : 0.f;
#pragma unroll
        for (int o = 8; o; o >>= 1) v += __shfl_xor_sync(0xffffffffu, v, o);
        if (tid == 0) redx[0] = rsqrtf(v);
    }
    __syncthreads();
    const float sc = redx[0];
    s[tid]       = make_float2(a0.x * sc, a0.y * sc);
    s[tid + 512] = make_float2(a1.x * sc, a1.y * sc);
    __syncthreads();

    apply_circuit_smem(s, g, tid);

    // measurement: per wire w, pairs split on bit p = 9-w
#pragma unroll
    for (int w = 0; w < NQ; ++w) {
        const int p   = 9 - w;
        const int bit = 1 << p;
        const int low = tid & (bit - 1);
        const int i0  = ((tid >> p) << (p + 1)) | low;
        const int i1  = i0 | bit;
        const float2 v0 = s[i0];
        const float2 v1 = s[i1];
        float xr = v0.x * v1.x + v0.y * v1.y;             // Re(conj(a0)*a1)
        float yi = v0.x * v1.y - v0.y * v1.x;             // Im(conj(a0)*a1)
        float zz = v0.x * v0.x + v0.y * v0.y - v1.x * v1.x - v1.y * v1.y;
#pragma unroll
        for (int o = 16; o; o >>= 1) {
            xr += __shfl_xor_sync(0xffffffffu, xr, o);
            yi += __shfl_xor_sync(0xffffffffu, yi, o);
            zz += __shfl_xor_sync(0xffffffffu, zz, o);
        }
        __syncthreads();
        if ((tid & 31) == 0) {
            redx[tid >> 5] = xr; redy[tid >> 5] = yi; redz[tid >> 5] = zz;
        }
        __syncthreads();
        if (tid < 32) {
            float vx = (tid < 16) ? redx[tid] : 0.f;
            float vy = (tid < 16) ? redy[tid] : 0.f;
            float vz = (tid < 16) ? redz[tid] : 0.f;
#pragma unroll
            for (int o = 8; o; o >>= 1) {
                vx += __shfl_xor_sync(0xffffffffu, vx, o);
                vy += __shfl_xor_sync(0xffffffffu, vy, o);
                vz += __shfl_xor_sync(0xffffffffu, vz, o);
            }
            if (tid == 0) {
                out[b * 30 + w]      = 2.f * vx;
                out[b * 30 + 10 + w] = 2.f * vy;
                out[b * 30 + 20 + w] = vz;
            }
        }
    }
}

// ----------------------------- launch ---------------------------------------
extern "C" void kernel_launch(void* const* d_in, const int* in_sizes, int n_in,
                              void* d_out, int out_size)
{
    const float* tokens = (const float*)d_in[0];  // (128, 32, 512)
    const float* W      = (const float*)d_in[1];  // (40, 512)
    const float* bias   = (const float*)d_in[2];  // (40,)
    const float* lre    = (const float*)d_in[3];  // (32,)
    const float* lim    = (const float*)d_in[4];  // (32,)
    const float* qsvt   = (const float*)d_in[5];  // (3,)
    const float* ffp    = (const float*)d_in[6];  // (40,)
    float* out          = (float*)d_out;          // (128, 30)

    wsim_kernel<true><<<NB * 4, 256>>>(tokens, W, bias, lre, lim);
    wsim_kernel<false><<<NB * 4, 256>>>(tokens, W, bias, lre, lim);
    final_kernel<<<NB, 512>>>(qsvt, ffp, out);
}